// round 6
// baseline (speedup 1.0000x reference)
#include <cuda_runtime.h>
#include <cstdint>

#define TT 4
#define BBATCH 32
#define CC 384
#define NN 196
#define MM 6272            // BBATCH*NN
#define HH 8
#define DD 48
#define DQKV 1152
#define TSTR (BBATCH*CC*NN)    // 2408448

typedef unsigned long long u64;
typedef unsigned int u32;

// packed f32x2 helpers (sm_103a FFMA2 only reachable via PTX)
#define FMA_F32X2(d, a, b) \
    asm("fma.rn.f32x2 %0, %1, %2, %3;" : "=l"(d) : "l"(a), "l"(b), "l"(d))
#define DUP_F32X2(d, f) \
    asm("mov.b64 %0, {%1, %1};" : "=l"(d) : "r"(__float_as_uint(f)))
#define UNPACK_F32X2(lo, hi, v) \
    asm("mov.b64 {%0, %1}, %2;" : "=r"(lo), "=r"(hi) : "l"(v))

// ---------------- scratch (device globals; no allocation allowed) ----------------
__device__ __align__(16) unsigned char g_spk[TT*MM*DQKV];            // spike bytes (q|k|v)
__device__ float g_attnspk[TT*BBATCH*CC*NN];                          // attn-LIF spikes
__device__ float g_Wt1152[CC*DQKV];                                   // transposed qkv weights [C][1152]
__device__ float g_Wt384[CC*CC];                                      // transposed wp [C][384]

// ---------------- weight transpose prep ----------------
__global__ void k_prepw(const float* __restrict__ wq, const float* __restrict__ wk,
                        const float* __restrict__ wv, const float* __restrict__ wp) {
    int i = blockIdx.x * 256 + threadIdx.x;
    if (i < CC*DQKV) {
        int c = i / DQKV, dg = i - c*DQKV;
        int ten = dg / CC, d = dg - ten*CC;
        const float* w = (ten == 0) ? wq : (ten == 1) ? wk : wv;
        g_Wt1152[i] = w[d*CC + c];
    } else {
        int k = i - CC*DQKV;
        if (k < CC*CC) {
            int c = k / CC, d = k - c*CC;
            g_Wt384[k] = wp[d*CC + c];
        }
    }
}

// ---------------- fused conv(1x1) + BN + LIF GEMM (FFMA2, smem-lean) ----------------
// BM=128 (positions), BN=64 (out ch), BK=8, 256 threads.
// Thread tile: 4 m (two f32x2 pairs) x 8 d x 4 t. 1.5 smem-bytes per FFMA2.
// All 4 time steps per thread -> LIF fused in epilogue.
// Strict sequential k-order per accumulator -> bit-identical outputs.
template<bool FINAL>
__global__ void __launch_bounds__(256, 1) k_conv_lif(
    const float* __restrict__ X,
    const float* __restrict__ sc0, const float* __restrict__ sc1, const float* __restrict__ sc2,
    const float* __restrict__ bi0, const float* __restrict__ bi1, const float* __restrict__ bi2,
    float* __restrict__ outF)
{
    constexpr int DTOT = FINAL ? CC : DQKV;
    const float* __restrict__ A  = FINAL ? g_attnspk : X;
    const float* __restrict__ Wt = FINAL ? g_Wt384 : g_Wt1152;

    __shared__ __align__(16) float As[2][TT][8][128];   // 32 KB
    __shared__ __align__(16) float Ws[2][8][64];        //  4 KB

    const int tid = threadIdx.x;
    const int m0 = blockIdx.x * 128;
    const int d0 = blockIdx.y * 64;

    // ---- loader coords ----
    const int lr = tid >> 5;            // k row within tile (0..7)
    const int lc = (tid & 31) * 4;      // m col base (0..124)
    const float* Apj[4];
    #pragma unroll
    for (int j = 0; j < 4; j++) {
        int mj = m0 + lc + j;
        int lb = mj / NN;
        int ln = mj - lb * NN;
        Apj[j] = A + (size_t)lb * CC * NN + ln;
    }
    const int wr = tid >> 5;            // k row (0..7)
    const int wc = (tid & 31) * 2;      // d col (0..62)

    // acc2[t][pair][j] : pair0 = m rows ty4+0/1, pair1 = ty4+2/3
    u64 acc2[TT][2][8];
    #pragma unroll
    for (int t = 0; t < TT; t++)
        #pragma unroll
        for (int p = 0; p < 2; p++)
            #pragma unroll
            for (int j = 0; j < 8; j++) acc2[t][p][j] = 0ull;

    float4 ra4[TT];
    float2 rwv;

    // ---- prologue: tile 0 ----
    #pragma unroll
    for (int t = 0; t < TT; t++) {
        ra4[t].x = Apj[0][(size_t)t*TSTR + (size_t)lr*NN];
        ra4[t].y = Apj[1][(size_t)t*TSTR + (size_t)lr*NN];
        ra4[t].z = Apj[2][(size_t)t*TSTR + (size_t)lr*NN];
        ra4[t].w = Apj[3][(size_t)t*TSTR + (size_t)lr*NN];
    }
    rwv = *(const float2*)&Wt[(size_t)wr*DTOT + d0 + wc];
    #pragma unroll
    for (int t = 0; t < TT; t++) *(float4*)&As[0][t][lr][lc] = ra4[t];
    *(float2*)&Ws[0][wr][wc] = rwv;
    __syncthreads();

    const int tx8 = (tid & 7) * 8;      // d sub-tile base
    const int ty4 = (tid >> 3) * 4;     // m sub-tile base

    int buf = 0;
    for (int kt = 0; kt < 48; kt++) {
        if (kt < 47) {
            int c0 = (kt + 1) * 8;
            #pragma unroll
            for (int t = 0; t < TT; t++) {
                ra4[t].x = Apj[0][(size_t)t*TSTR + (size_t)(c0 + lr)*NN];
                ra4[t].y = Apj[1][(size_t)t*TSTR + (size_t)(c0 + lr)*NN];
                ra4[t].z = Apj[2][(size_t)t*TSTR + (size_t)(c0 + lr)*NN];
                ra4[t].w = Apj[3][(size_t)t*TSTR + (size_t)(c0 + lr)*NN];
            }
            rwv = *(const float2*)&Wt[(size_t)(c0 + wr)*DTOT + d0 + wc];
        }
        #pragma unroll
        for (int k = 0; k < 8; k++) {
            float4 w0 = *(const float4*)&Ws[buf][k][tx8];
            float4 w1 = *(const float4*)&Ws[buf][k][tx8 + 4];
            u64 b2[8];
            DUP_F32X2(b2[0], w0.x); DUP_F32X2(b2[1], w0.y);
            DUP_F32X2(b2[2], w0.z); DUP_F32X2(b2[3], w0.w);
            DUP_F32X2(b2[4], w1.x); DUP_F32X2(b2[5], w1.y);
            DUP_F32X2(b2[6], w1.z); DUP_F32X2(b2[7], w1.w);
            #pragma unroll
            for (int t = 0; t < TT; t++) {
                ulonglong2 av = *(const ulonglong2*)&As[buf][t][k][ty4];
                #pragma unroll
                for (int j = 0; j < 8; j++) {
                    FMA_F32X2(acc2[t][0][j], av.x, b2[j]);
                    FMA_F32X2(acc2[t][1][j], av.y, b2[j]);
                }
            }
        }
        if (kt < 47) {
            int nb = buf ^ 1;
            #pragma unroll
            for (int t = 0; t < TT; t++) *(float4*)&As[nb][t][lr][lc] = ra4[t];
            *(float2*)&Ws[nb][wr][wc] = rwv;
        }
        __syncthreads();
        buf ^= 1;
    }

    // ---- epilogue: BN + LIF (exact reference op sequence; no fma contraction) ----
    int dl = d0 + tx8;
    const float *sc, *bi;
    if (FINAL) { sc = sc0; bi = bi0; }
    else {
        int ten = d0 / CC;
        dl = d0 - ten*CC + tx8;
        sc = (ten == 0) ? sc0 : (ten == 1) ? sc1 : sc2;
        bi = (ten == 0) ? bi0 : (ten == 1) ? bi1 : bi2;
    }
    float scv[8], biv[8];
    #pragma unroll
    for (int j = 0; j < 8; j++) { scv[j] = sc[dl + j]; biv[j] = bi[dl + j]; }

    #pragma unroll
    for (int i = 0; i < 4; i++) {
        const int p = i >> 1, hi = i & 1;
        const int m = m0 + ty4 + i;
        float v[8];
        #pragma unroll
        for (int j = 0; j < 8; j++) v[j] = 0.f;
        if (!FINAL) {
            #pragma unroll
            for (int t = 0; t < TT; t++) {
                u64 pk = 0ull;
                #pragma unroll
                for (int j = 0; j < 8; j++) {
                    u32 lo, hh;
                    UNPACK_F32X2(lo, hh, acc2[t][p][j]);
                    float a = __uint_as_float(hi ? hh : lo);
                    float y = __fadd_rn(__fmul_rn(a, scv[j]), biv[j]);
                    v[j] = __fadd_rn(v[j], __fmul_rn(__fadd_rn(y, -v[j]), 0.5f));
                    if (v[j] >= 1.0f) { pk |= 1ull << (8*j); v[j] = 0.f; }
                }
                *(u64*)&g_spk[((size_t)t*MM + m)*DQKV + d0 + tx8] = pk;
            }
        } else {
            int b_o = m / NN, n_o = m - b_o*NN;
            #pragma unroll
            for (int t = 0; t < TT; t++) {
                #pragma unroll
                for (int j = 0; j < 8; j++) {
                    u32 lo, hh;
                    UNPACK_F32X2(lo, hh, acc2[t][p][j]);
                    float a = __uint_as_float(hi ? hh : lo);
                    float y = __fadd_rn(__fmul_rn(a, scv[j]), biv[j]);
                    v[j] = __fadd_rn(v[j], __fmul_rn(__fadd_rn(y, -v[j]), 0.5f));
                    bool hhit = v[j] >= 1.0f;
                    outF[(((size_t)t*BBATCH + b_o)*CC + (dl + j))*NN + n_o] = hhit ? 1.0f : 0.0f;
                    if (hhit) v[j] = 0.f;
                }
            }
        }
    }
}

// ---------------- attention (pack fused): out = q @ (k^T v) * 0.125, LIF(0.5) ----------------
// Integer-exact: spikes binary, G entries <=196, sums <=9408 < 2^16.
__global__ void __launch_bounds__(256) k_attn() {
    __shared__ unsigned long long qm[TT][NN];
    __shared__ unsigned long long km[TT][NN];
    __shared__ unsigned long long vm[TT][NN];
    __shared__ unsigned int kT[TT][DD][7];
    __shared__ unsigned int vT[TT][DD][7];
    __shared__ __align__(16) unsigned int Gp[TT][DD][24];   // two u16 sums per word

    const int b = blockIdx.x, h = blockIdx.y;
    const int tid = threadIdx.x;

    // ---- pack spike bytes -> 48-bit masks (byte-gather multiply trick) ----
    for (int e = tid; e < 3*TT*NN; e += 256) {
        int ten = e / (TT*NN);
        int r = e - ten*(TT*NN);
        int t = r / NN, n = r - t*NN;
        int m = b*NN + n;
        const uint4* p = (const uint4*)(g_spk + ((size_t)t*MM + m)*DQKV + ten*CC + h*DD);
        unsigned long long mask = 0;
        #pragma unroll
        for (int q = 0; q < 3; q++) {
            uint4 u = p[q];
            unsigned n0 = (u.x * 0x01020408u) >> 24;
            unsigned n1 = (u.y * 0x01020408u) >> 24;
            unsigned n2 = (u.z * 0x01020408u) >> 24;
            unsigned n3 = (u.w * 0x01020408u) >> 24;
            unsigned hw = (n0 & 0xF) | ((n1 & 0xF) << 4) | ((n2 & 0xF) << 8) | ((n3 & 0xF) << 12);
            mask |= (unsigned long long)hw << (16*q);
        }
        if (ten == 0) qm[t][n] = mask;
        else if (ten == 1) km[t][n] = mask;
        else vm[t][n] = mask;
    }
    __syncthreads();

    // ---- bit-transpose k,v via warp ballot: 8 warps = 4 t x {k,v} ----
    {
        int w = tid >> 5, lane = tid & 31;
        int t = w >> 1;
        int isv = w & 1;
        for (int g = 0; g < 7; g++) {
            int m = g*32 + lane;
            unsigned long long mk = 0;
            if (m < NN) mk = isv ? vm[t][m] : km[t][m];
            #pragma unroll
            for (int j = 0; j < DD; j++) {
                unsigned bal = __ballot_sync(0xffffffffu, (unsigned)((mk >> j) & 1ull));
                if (lane == 0) { if (isv) vT[t][j][g] = bal; else kT[t][j][g] = bal; }
            }
        }
    }
    __syncthreads();

    // ---- Gp[t][j][p] = G[j][2p] | G[j][2p+1]<<16 via AND+popc ----
    for (int e = tid; e < TT*DD*24; e += 256) {
        int t = e / (DD*24), r = e - t*(DD*24);
        int j = r / 24, p = r - j*24;
        int s0 = 0, s1 = 0;
        #pragma unroll
        for (int g = 0; g < 7; g++) {
            s0 += __popc(kT[t][j][g] & vT[t][2*p][g]);
            s1 += __popc(kT[t][j][g] & vT[t][2*p + 1][g]);
        }
        Gp[t][j][p] = (unsigned)s0 | ((unsigned)s1 << 16);
    }
    __syncthreads();

    // ---- out[n, 8g..8g+7]: masked packed adds over j; LIF(0.5); write fp32 spikes ----
    for (int e = tid; e < 6*NN; e += 256) {
        int g = e / NN, n = e - g*NN;
        int p0 = g * 4;
        float v[8];
        #pragma unroll
        for (int d = 0; d < 8; d++) v[d] = 0.f;
        #pragma unroll
        for (int t = 0; t < TT; t++) {
            unsigned long long q = qm[t][n];
            unsigned ql = (unsigned)q, qh = (unsigned)(q >> 32);
            unsigned S[4] = {0u, 0u, 0u, 0u};
            #pragma unroll
            for (int j = 0; j < 32; j++) {
                unsigned msk = (unsigned)((int)(ql << (31 - j)) >> 31);
                uint4 gw = *(const uint4*)&Gp[t][j][p0];
                S[0] += gw.x & msk; S[1] += gw.y & msk;
                S[2] += gw.z & msk; S[3] += gw.w & msk;
            }
            #pragma unroll
            for (int j = 0; j < 16; j++) {
                unsigned msk = (unsigned)((int)(qh << (31 - j)) >> 31);
                uint4 gw = *(const uint4*)&Gp[t][32 + j][p0];
                S[0] += gw.x & msk; S[1] += gw.y & msk;
                S[2] += gw.z & msk; S[3] += gw.w & msk;
            }
            float* outp = &g_attnspk[(((size_t)t*BBATCH + b)*CC + h*DD + 8*g)*NN + n];
            #pragma unroll
            for (int pp = 0; pp < 4; pp++) {
                int s0 = (int)(S[pp] & 0xFFFFu);
                int s1 = (int)(S[pp] >> 16);
                float x0 = (float)s0 * 0.125f;
                float x1 = (float)s1 * 0.125f;
                int d0i = 2*pp, d1i = 2*pp + 1;
                v[d0i] = __fadd_rn(v[d0i], __fmul_rn(__fadd_rn(x0, -v[d0i]), 0.5f));
                v[d1i] = __fadd_rn(v[d1i], __fmul_rn(__fadd_rn(x1, -v[d1i]), 0.5f));
                bool h0 = v[d0i] >= 0.5f, h1 = v[d1i] >= 0.5f;
                outp[(size_t)d0i * NN] = h0 ? 1.0f : 0.0f;
                outp[(size_t)d1i * NN] = h1 ? 1.0f : 0.0f;
                if (h0) v[d0i] = 0.f;
                if (h1) v[d1i] = 0.f;
            }
        }
    }
}

// ---------------- launch ----------------
extern "C" void kernel_launch(void* const* d_in, const int* in_sizes, int n_in,
                              void* d_out, int out_size) {
    const float* x  = (const float*)d_in[0];
    const float* wq = (const float*)d_in[1];
    const float* sq = (const float*)d_in[2];
    const float* bq = (const float*)d_in[3];
    const float* wk = (const float*)d_in[4];
    const float* sk = (const float*)d_in[5];
    const float* bk = (const float*)d_in[6];
    const float* wv = (const float*)d_in[7];
    const float* sv = (const float*)d_in[8];
    const float* bv = (const float*)d_in[9];
    const float* wp = (const float*)d_in[10];
    const float* sp = (const float*)d_in[11];
    const float* bp = (const float*)d_in[12];
    float* out = (float*)d_out;

    k_prepw<<<(CC*DQKV + CC*CC + 255)/256, 256>>>(wq, wk, wv, wp);
    k_conv_lif<false><<<dim3(49, 18), 256>>>(x, sq, sk, sv, bq, bk, bv, nullptr);
    k_attn<<<dim3(BBATCH, HH), 256>>>();
    k_conv_lif<true><<<dim3(49, 6), 256>>>(x, sp, sp, sp, bp, bp, bp, out);
}